// round 11
// baseline (speedup 1.0000x reference)
#include <cuda_runtime.h>
#include <cstdint>

// ============================================================================
// SAE forward, sm_103 base target (SIMT, packed fp32 fma.rn.f32x2):
// encode: 128 CTAs x 256 thr. A^T (k-major) resident in smem; B 32-col chunks
// [k][col] double-buffered. Thread tile 8x8 via diagonal-packed FMA2, k-split 4
// inside the warp (shfl butterfly reduce). Fused streaming top-32.
// decode: margin-classified exact selection + sparse gather decode.
// ============================================================================

static constexpr int SM_AT  = 0;                 // A^T [256][132] f32 = 135168 B
static constexpr int SM_B   = 135168;            // 2 x [256][34] f32 = 69632 B
static constexpr int B_BUF  = 34816;
static constexpr int SM_ACC = 204800;            // [128][34] f32 = 17408 B
static constexpr int SMEM_SZ = 222208;
static constexpr float MARG2 = 2e-4f;

__device__ unsigned long long g_topp[8192 * 64];

__device__ __forceinline__ uint32_t smem_u32(const void* p) {
    uint32_t a;
    asm("{ .reg .u64 t; cvta.to.shared.u64 t, %1; cvt.u32.u64 %0, t; }" : "=r"(a) : "l"(p));
    return a;
}
#define CPASYNC4(dst, src) \
    asm volatile("cp.async.ca.shared.global [%0], [%1], 4;" :: "r"(dst), "l"(src) : "memory")
#define CPCOMMIT() asm volatile("cp.async.commit_group;" ::: "memory")
#define CPWAIT1()  asm volatile("cp.async.wait_group 1;" ::: "memory")
#define CPWAIT0()  asm volatile("cp.async.wait_group 0;" ::: "memory")

#define FMA2(d, a, b) \
    asm("fma.rn.f32x2 %0, %1, %2, %0;" : "+l"(d) : "l"(a), "l"(b))
#define PACK2(d, x, y) \
    asm("mov.b64 %0, {%1, %2};" : "=l"(d) : "f"(x), "f"(y))
#define UNPACK2(x, y, d) \
    asm("mov.b64 {%0, %1}, %2;" : "=f"(x), "=f"(y) : "l"(d))

// ============================================================================
// encode: grid (64 M-tiles, 2 H-halves), 256 threads.
// lane mapping: ks = tid&3 (k-slice of 64), tc = (tid>>2)&3 (8 cols), tr = tid>>4
// (8 rows). Warp spans 4 ks x 4 tc x 2 tr -> butterfly over ks is intra-warp.
// ============================================================================
__global__ void __launch_bounds__(256, 1)
encode_topk(const float* __restrict__ x, const float* __restrict__ W_enc,
            const float* __restrict__ b_enc, const float* __restrict__ b_dec) {
    extern __shared__ char smp[];
    const uint32_t sb = smem_u32(smp);
    const int tid = threadIdx.x;
    const int half = blockIdx.y, mrow0 = blockIdx.x * 128;
    const int hb0 = half * 4096;

    // ---- A^T[k][r] = x[mrow0+r][k] - b_dec[k], word = 132*k + r ----
    {
        const float4* x4 = reinterpret_cast<const float4*>(x);
        const float4* bd4 = reinterpret_cast<const float4*>(b_dec);
        float* at = reinterpret_cast<float*>(smp + SM_AT);
        #pragma unroll
        for (int it = 0; it < 32; it++) {
            int u = tid + it * 256;
            int r = u & 127, c4 = u >> 7;
            float4 v = x4[(size_t)(mrow0 + r) * 64 + c4];
            float4 bd = bd4[c4];
            float* p = at + (4 * c4) * 132 + r;
            p[0]   = v.x - bd.x;
            p[132] = v.y - bd.y;
            p[264] = v.z - bd.z;
            p[396] = v.w - bd.w;
        }
    }
    // ---- prefetch B chunk 0: B[k][c] word = 34*k + c ----
    {
        const float* s0 = W_enc + (size_t)hb0 * 256;
        #pragma unroll
        for (int it = 0; it < 32; it++) {
            int q = tid + it * 256, cl = q >> 8, k = q & 255;
            CPASYNC4(sb + SM_B + (uint32_t)(34 * k + cl) * 4, s0 + cl * 256 + k);
        }
        CPCOMMIT();
    }

    const int ks = tid & 3, tc = (tid >> 2) & 3, tr = tid >> 4;
    const char* Ab = smp + SM_AT + ks * 64 * 528 + tr * 32;
    float* accf = reinterpret_cast<float*>(smp + SM_ACC);

    unsigned long long L[32], pmin = 0ull;
    int amin = 0;

    for (int c = 0; c < 128; c++) {
        const int buf = c & 1;
        if (c + 1 < 128) {
            const float* s0 = W_enc + (size_t)(hb0 + (c + 1) * 32) * 256;
            const uint32_t db = sb + SM_B + ((c + 1) & 1) * B_BUF;
            #pragma unroll
            for (int it = 0; it < 32; it++) {
                int q = tid + it * 256, cl = q >> 8, k = q & 255;
                CPASYNC4(db + (uint32_t)(34 * k + cl) * 4, s0 + cl * 256 + k);
            }
            CPCOMMIT();
            CPWAIT1();
        } else {
            CPWAIT0();
        }
        __syncthreads();   // B[c] visible; accf topk-read of c-1 done

        // ---- GEMM 8x8 tile, k-slice of 64, diagonal-packed FMA2 ----
        const char* Bp = smp + SM_B + buf * B_BUF + ks * 64 * 136 + tc * 32;
        unsigned long long d0[4][4], d1[4][4];
        #pragma unroll
        for (int i = 0; i < 4; i++)
            #pragma unroll
            for (int p = 0; p < 4; p++) { d0[i][p] = 0ull; d1[i][p] = 0ull; }
        #pragma unroll 2
        for (int kk = 0; kk < 64; kk++) {
            ulonglong2 aA = *reinterpret_cast<const ulonglong2*>(Ab + kk * 528);
            ulonglong2 aB = *reinterpret_cast<const ulonglong2*>(Ab + kk * 528 + 16);
            #pragma unroll
            for (int p = 0; p < 4; p++) {
                unsigned long long bp =
                    *reinterpret_cast<const unsigned long long*>(Bp + kk * 136 + p * 8);
                float bl, bh;
                UNPACK2(bl, bh, bp);
                unsigned long long bs;
                PACK2(bs, bh, bl);
                FMA2(d0[0][p], aA.x, bp); FMA2(d1[0][p], aA.x, bs);
                FMA2(d0[1][p], aA.y, bp); FMA2(d1[1][p], aA.y, bs);
                FMA2(d0[2][p], aB.x, bp); FMA2(d1[2][p], aB.x, bs);
                FMA2(d0[3][p], aB.y, bp); FMA2(d1[3][p], aB.y, bs);
            }
        }
        // ---- unpack, butterfly-reduce over ks lanes, write i==ks rows ----
        {
            float v00[4][4], v01[4][4], v10[4][4], v11[4][4];
            #pragma unroll
            for (int i = 0; i < 4; i++)
                #pragma unroll
                for (int p = 0; p < 4; p++) {
                    UNPACK2(v00[i][p], v01[i][p], d0[i][p]);
                    UNPACK2(v10[i][p], v11[i][p], d1[i][p]);
                }
            #pragma unroll
            for (int i = 0; i < 4; i++)
                #pragma unroll
                for (int p = 0; p < 4; p++) {
                    v00[i][p] += __shfl_xor_sync(0xffffffffu, v00[i][p], 1);
                    v00[i][p] += __shfl_xor_sync(0xffffffffu, v00[i][p], 2);
                    v01[i][p] += __shfl_xor_sync(0xffffffffu, v01[i][p], 1);
                    v01[i][p] += __shfl_xor_sync(0xffffffffu, v01[i][p], 2);
                    v10[i][p] += __shfl_xor_sync(0xffffffffu, v10[i][p], 1);
                    v10[i][p] += __shfl_xor_sync(0xffffffffu, v10[i][p], 2);
                    v11[i][p] += __shfl_xor_sync(0xffffffffu, v11[i][p], 1);
                    v11[i][p] += __shfl_xor_sync(0xffffffffu, v11[i][p], 2);
                }
            // d0.lo=(r0,c0) d0.hi=(r1,c1) d1.lo=(r0,c1) d1.hi=(r1,c0)
            #pragma unroll
            for (int i = 0; i < 4; i++) {
                if (i == ks) {
                    const int r0 = 8 * tr + 2 * i;
                    #pragma unroll
                    for (int p = 0; p < 4; p++) {
                        float2 lo; lo.x = v00[i][p]; lo.y = v10[i][p];
                        float2 hi; hi.x = v11[i][p]; hi.y = v01[i][p];
                        *reinterpret_cast<float2*>(accf + r0 * 34 + 8 * tc + 2 * p) = lo;
                        *reinterpret_cast<float2*>(accf + (r0 + 1) * 34 + 8 * tc + 2 * p) = hi;
                    }
                }
            }
        }
        __syncthreads();

        // ---- streaming top-32 (thread per row, 32 new values) ----
        if (tid < 128) {
            const float* ar = accf + tid * 34;
            const int hbase = hb0 + c * 32;
            if (c == 0) {
                #pragma unroll
                for (int n = 0; n < 32; n++) {
                    float v = fmaxf(ar[n] + __ldg(b_enc + hbase + n), 0.0f);
                    L[n] = ((unsigned long long)__float_as_uint(v) << 32) |
                           (unsigned)(8191 - (hbase + n));
                }
                pmin = L[0]; amin = 0;
                #pragma unroll
                for (int j = 1; j < 32; j++)
                    if (L[j] < pmin) { pmin = L[j]; amin = j; }
            } else {
                #pragma unroll 4
                for (int n = 0; n < 32; n++) {
                    float v = fmaxf(ar[n] + __ldg(b_enc + hbase + n), 0.0f);
                    unsigned long long p =
                        ((unsigned long long)__float_as_uint(v) << 32) |
                        (unsigned)(8191 - (hbase + n));
                    if (p > pmin) {
                        #pragma unroll
                        for (int j = 0; j < 32; j++) if (j == amin) L[j] = p;
                        pmin = L[0]; amin = 0;
                        #pragma unroll
                        for (int j = 1; j < 32; j++)
                            if (L[j] < pmin) { pmin = L[j]; amin = j; }
                    }
                }
            }
        }
    }
    if (tid < 128) {
        const size_t base = (size_t)(mrow0 + tid) * 64 + half * 32;
        #pragma unroll 1
        for (int s = 0; s < 32; s++) g_topp[base + s] = L[s];
    }
}

// ============================================================================
// decode: grid 8192, block 256 — classify 64 candidates, fp64 rescue ambiguous,
// exact select top-32, sparse gather decode.
// ============================================================================
__global__ void __launch_bounds__(256)
decode(const float* __restrict__ x, const float* __restrict__ W_enc,
       const float* __restrict__ b_enc, const float* __restrict__ W_dec,
       const float* __restrict__ b_dec, float* __restrict__ out) {
    __shared__ float sx[256], sa[64], selv[32];
    __shared__ int si[64], cls[64], seli[32];
    __shared__ double se[64];
    const int row = blockIdx.x, t = threadIdx.x;

    sx[t] = x[(size_t)row * 256 + t] - b_dec[t];
    if (t < 64) {
        unsigned long long p = g_topp[(size_t)row * 64 + t];
        sa[t] = __uint_as_float((uint32_t)(p >> 32));
        si[t] = 8191 - (int)(p & 0xFFFFFFFFu);
    }
    __syncthreads();
    if (t < 64) {
        float at = sa[t];
        int pos = 0, cert = 0;
        #pragma unroll 1
        for (int j = 0; j < 64; j++) {
            if (j == t) continue;
            pos  += (sa[j] >= at - MARG2);
            cert += (sa[j] >  at + MARG2);
        }
        cls[t] = (pos <= 31) ? 2 : (cert >= 32 ? 0 : 1);
    }
    __syncthreads();
    if (t < 64 && cls[t] == 1) {
        const float* wr = W_enc + (size_t)si[t] * 256;
        double s0 = 0, s1 = 0, s2 = 0, s3 = 0;
        #pragma unroll 1
        for (int d = 0; d < 256; d += 4) {
            s0 += (double)sx[d]     * (double)wr[d];
            s1 += (double)sx[d + 1] * (double)wr[d + 1];
            s2 += (double)sx[d + 2] * (double)wr[d + 2];
            s3 += (double)sx[d + 3] * (double)wr[d + 3];
        }
        double e = s0 + s1 + s2 + s3 + (double)b_enc[si[t]];
        se[t] = e > 0.0 ? e : 0.0;
    }
    __syncthreads();
    if (t == 0) {
        int ns = 0;
        bool taken[64];
        #pragma unroll 1
        for (int j = 0; j < 64; j++) {
            taken[j] = false;
            if (cls[j] == 2 && ns < 32) { seli[ns] = si[j]; selv[ns] = sa[j]; ns++; }
        }
        while (ns < 32) {
            int best = -1, bi = 1 << 30;
            double bv = -1.0;
            #pragma unroll 1
            for (int j = 0; j < 64; j++) {
                if (cls[j] == 1 && !taken[j]) {
                    if (se[j] > bv || (se[j] == bv && si[j] < bi)) {
                        best = j; bv = se[j]; bi = si[j];
                    }
                }
            }
            if (best < 0) { seli[ns] = 0; selv[ns] = 0.0f; ns++; continue; }
            taken[best] = true;
            seli[ns] = si[best]; selv[ns] = (float)se[best]; ns++;
        }
    }
    __syncthreads();
    float acc = b_dec[t];
    #pragma unroll 8
    for (int k = 0; k < 32; k++)
        acc = fmaf(selv[k], W_dec[(size_t)seli[k] * 256 + t], acc);
    out[(size_t)row * 256 + t] = acc;
}

// ============================================================================
extern "C" void kernel_launch(void* const* d_in, const int* in_sizes, int n_in,
                              void* d_out, int out_size) {
    const float* x     = (const float*)d_in[0];
    const float* W_enc = (const float*)d_in[1];
    const float* b_enc = (const float*)d_in[2];
    const float* W_dec = (const float*)d_in[3];
    const float* b_dec = (const float*)d_in[4];
    float* out = (float*)d_out;

    cudaFuncSetAttribute(encode_topk, cudaFuncAttributeMaxDynamicSharedMemorySize, SMEM_SZ);
    encode_topk<<<dim3(64, 2), 256, SMEM_SZ>>>(x, W_enc, b_enc, b_dec);
    decode<<<8192, 256>>>(x, W_enc, b_enc, W_dec, b_dec, out);
}

// round 12
// speedup vs baseline: 1.2098x; 1.2098x over previous
#include <cuda_runtime.h>
#include <cstdint>

// ============================================================================
// SAE forward, sm_103 base target (SIMT, packed fp32 fma.rn.f32x2):
// encode: 128 CTAs x 256 thr. A^T (k-major, stride 128) resident in smem.
// B 32-col chunks, col-pair interleaved [cp][k][2], double buffered (cp.async).
// Thread tile 4 rows x 4 cols via diagonal-packed FMA2 (8 FFMA2/k, no shuffles).
// Fused streaming top-32; decode = margin-classified exact select + gather.
// nop kernels shift ncu -s 5 parity so encode (not decode) gets profiled.
// ============================================================================

static constexpr int SM_AT  = 0;                  // A^T [256][128] f32 = 131072 B
static constexpr int SM_B   = 131072;             // 2 x (16 cp x 514 f32) = 65792 B
static constexpr int B_BUF  = 32896;
static constexpr int SM_ACC = 196864;             // [128][34] f32 = 17408 B
static constexpr int SMEM_SZ = 214272;
static constexpr float MARG2 = 2e-4f;

__device__ unsigned long long g_topp[8192 * 64];

__device__ __forceinline__ uint32_t smem_u32(const void* p) {
    uint32_t a;
    asm("{ .reg .u64 t; cvta.to.shared.u64 t, %1; cvt.u32.u64 %0, t; }" : "=r"(a) : "l"(p));
    return a;
}
#define CPASYNC4(dst, src) \
    asm volatile("cp.async.ca.shared.global [%0], [%1], 4;" :: "r"(dst), "l"(src) : "memory")
#define CPCOMMIT() asm volatile("cp.async.commit_group;" ::: "memory")
#define CPWAIT1()  asm volatile("cp.async.wait_group 1;" ::: "memory")
#define CPWAIT0()  asm volatile("cp.async.wait_group 0;" ::: "memory")

#define FMA2(d, a, b) \
    asm("fma.rn.f32x2 %0, %1, %2, %0;" : "+l"(d) : "l"(a), "l"(b))
#define PACK2(d, x, y) \
    asm("mov.b64 %0, {%1, %2};" : "=l"(d) : "f"(x), "f"(y))
#define UNPACK2(x, y, d) \
    asm("mov.b64 {%0, %1}, %2;" : "=f"(x), "=f"(y) : "l"(d))

__global__ void nop_k() {}

// ============================================================================
// encode: grid (64 M-tiles, 2 H-halves), 256 threads.
// rg = tid>>3 (rows 4rg..4rg+3), cg = tid&7 (col-pairs cg and cg+8 of 16).
// ============================================================================
__global__ void __launch_bounds__(256, 1)
encode_topk(const float* __restrict__ x, const float* __restrict__ W_enc,
            const float* __restrict__ b_enc, const float* __restrict__ b_dec) {
    extern __shared__ char smp[];
    const uint32_t sb = smem_u32(smp);
    const int tid = threadIdx.x;
    const int half = blockIdx.y, mrow0 = blockIdx.x * 128;
    const int hb0 = half * 4096;

    // ---- A^T[k][r] = x[mrow0+r][k] - b_dec[k]; word = 128*k + r ----
    {
        const float4* x4 = reinterpret_cast<const float4*>(x);
        const float4* bd4 = reinterpret_cast<const float4*>(b_dec);
        float* at = reinterpret_cast<float*>(smp + SM_AT);
        #pragma unroll
        for (int it = 0; it < 32; it++) {
            int u = tid + it * 256;
            int r = u & 127, c4 = u >> 7;
            float4 v = x4[(size_t)(mrow0 + r) * 64 + c4];
            float4 bd = bd4[c4];
            float* p = at + (4 * c4) * 128 + r;
            p[0]   = v.x - bd.x;
            p[128] = v.y - bd.y;
            p[256] = v.z - bd.z;
            p[384] = v.w - bd.w;
        }
    }
    // ---- prefetch B chunk 0: word = (c>>1)*514 + 2k + (c&1) ----
    {
        const float* s0 = W_enc + (size_t)hb0 * 256;
        #pragma unroll
        for (int it = 0; it < 32; it++) {
            int q = tid + it * 256, cl = q >> 8, k = q & 255;
            uint32_t w = (uint32_t)((cl >> 1) * 514 + 2 * k + (cl & 1));
            CPASYNC4(sb + SM_B + w * 4, s0 + cl * 256 + k);
        }
        CPCOMMIT();
    }

    const int rg = tid >> 3, cg = tid & 7;
    const char* Ab = smp + SM_AT + rg * 16;
    float* accf = reinterpret_cast<float*>(smp + SM_ACC);

    unsigned long long L[32], pmin = 0ull;
    int amin = 0;

    for (int c = 0; c < 128; c++) {
        const int buf = c & 1;
        if (c + 1 < 128) {
            const float* s0 = W_enc + (size_t)(hb0 + (c + 1) * 32) * 256;
            const uint32_t db = sb + SM_B + ((c + 1) & 1) * B_BUF;
            #pragma unroll
            for (int it = 0; it < 32; it++) {
                int q = tid + it * 256, cl = q >> 8, k = q & 255;
                uint32_t w = (uint32_t)((cl >> 1) * 514 + 2 * k + (cl & 1));
                CPASYNC4(db + w * 4, s0 + cl * 256 + k);
            }
            CPCOMMIT();
            CPWAIT1();
        } else {
            CPWAIT0();
        }
        __syncthreads();   // B[c] visible; accf topk-read of c-1 done

        // ---- GEMM 4x4 tile, diagonal-packed FMA2 ----
        const char* Bp0 = smp + SM_B + buf * B_BUF + cg * 514 * 4;
        const char* Bp1 = Bp0 + 8 * 514 * 4;
        unsigned long long d000 = 0, d010 = 0, d100 = 0, d110 = 0;
        unsigned long long d001 = 0, d011 = 0, d101 = 0, d111 = 0;
        #pragma unroll 4
        for (int k = 0; k < 256; k++) {
            ulonglong2 a = *reinterpret_cast<const ulonglong2*>(Ab + k * 512);
            unsigned long long b0 = *reinterpret_cast<const unsigned long long*>(Bp0 + k * 8);
            unsigned long long b1 = *reinterpret_cast<const unsigned long long*>(Bp1 + k * 8);
            float l0, h0, l1, h1;
            UNPACK2(l0, h0, b0);
            UNPACK2(l1, h1, b1);
            unsigned long long s0, s1;
            PACK2(s0, h0, l0);
            PACK2(s1, h1, l1);
            FMA2(d000, a.x, b0); FMA2(d100, a.x, s0);
            FMA2(d010, a.y, b0); FMA2(d110, a.y, s0);
            FMA2(d001, a.x, b1); FMA2(d101, a.x, s1);
            FMA2(d011, a.y, b1); FMA2(d111, a.y, s1);
        }
        // ---- unpack diagonals -> ACC[row][col], stride 34 ----
        // d0 lo=(r,c0) hi=(r+1,c1); d1 lo=(r,c1) hi=(r+1,c0)
        {
            const int r0 = 4 * rg;
            float e0, e1, f0, f1;
            float2 v;
            // i=0 (rows r0, r0+1), p=0 (cols 2cg, 2cg+1)
            UNPACK2(e0, e1, d000); UNPACK2(f0, f1, d100);
            v.x = e0; v.y = f0; *reinterpret_cast<float2*>(accf + r0 * 34 + 2 * cg) = v;
            v.x = f1; v.y = e1; *reinterpret_cast<float2*>(accf + (r0 + 1) * 34 + 2 * cg) = v;
            // i=1 (rows r0+2, r0+3), p=0
            UNPACK2(e0, e1, d010); UNPACK2(f0, f1, d110);
            v.x = e0; v.y = f0; *reinterpret_cast<float2*>(accf + (r0 + 2) * 34 + 2 * cg) = v;
            v.x = f1; v.y = e1; *reinterpret_cast<float2*>(accf + (r0 + 3) * 34 + 2 * cg) = v;
            // i=0, p=1 (cols 2cg+16, 2cg+17)
            UNPACK2(e0, e1, d001); UNPACK2(f0, f1, d101);
            v.x = e0; v.y = f0; *reinterpret_cast<float2*>(accf + r0 * 34 + 2 * cg + 16) = v;
            v.x = f1; v.y = e1; *reinterpret_cast<float2*>(accf + (r0 + 1) * 34 + 2 * cg + 16) = v;
            // i=1, p=1
            UNPACK2(e0, e1, d011); UNPACK2(f0, f1, d111);
            v.x = e0; v.y = f0; *reinterpret_cast<float2*>(accf + (r0 + 2) * 34 + 2 * cg + 16) = v;
            v.x = f1; v.y = e1; *reinterpret_cast<float2*>(accf + (r0 + 3) * 34 + 2 * cg + 16) = v;
        }
        __syncthreads();

        // ---- streaming top-32 (thread per row, 32 new values) ----
        if (tid < 128) {
            const float* ar = accf + tid * 34;
            const int hbase = hb0 + c * 32;
            if (c == 0) {
                #pragma unroll
                for (int n = 0; n < 32; n++) {
                    float v = fmaxf(ar[n] + __ldg(b_enc + hbase + n), 0.0f);
                    L[n] = ((unsigned long long)__float_as_uint(v) << 32) |
                           (unsigned)(8191 - (hbase + n));
                }
                pmin = L[0]; amin = 0;
                #pragma unroll
                for (int j = 1; j < 32; j++)
                    if (L[j] < pmin) { pmin = L[j]; amin = j; }
            } else {
                #pragma unroll 4
                for (int n = 0; n < 32; n++) {
                    float v = fmaxf(ar[n] + __ldg(b_enc + hbase + n), 0.0f);
                    unsigned long long p =
                        ((unsigned long long)__float_as_uint(v) << 32) |
                        (unsigned)(8191 - (hbase + n));
                    if (p > pmin) {
                        #pragma unroll
                        for (int j = 0; j < 32; j++) if (j == amin) L[j] = p;
                        pmin = L[0]; amin = 0;
                        #pragma unroll
                        for (int j = 1; j < 32; j++)
                            if (L[j] < pmin) { pmin = L[j]; amin = j; }
                    }
                }
            }
        }
    }
    if (tid < 128) {
        const size_t base = (size_t)(mrow0 + tid) * 64 + half * 32;
        #pragma unroll 1
        for (int s = 0; s < 32; s++) g_topp[base + s] = L[s];
    }
}

// ============================================================================
// decode: grid 8192, block 256 — classify 64 candidates, fp64 rescue ambiguous,
// exact select top-32, sparse gather decode.
// ============================================================================
__global__ void __launch_bounds__(256)
decode(const float* __restrict__ x, const float* __restrict__ W_enc,
       const float* __restrict__ b_enc, const float* __restrict__ W_dec,
       const float* __restrict__ b_dec, float* __restrict__ out) {
    __shared__ float sx[256], sa[64], selv[32];
    __shared__ int si[64], cls[64], seli[32];
    __shared__ double se[64];
    const int row = blockIdx.x, t = threadIdx.x;

    sx[t] = x[(size_t)row * 256 + t] - b_dec[t];
    if (t < 64) {
        unsigned long long p = g_topp[(size_t)row * 64 + t];
        sa[t] = __uint_as_float((uint32_t)(p >> 32));
        si[t] = 8191 - (int)(p & 0xFFFFFFFFu);
    }
    __syncthreads();
    if (t < 64) {
        float at = sa[t];
        int pos = 0, cert = 0;
        #pragma unroll 1
        for (int j = 0; j < 64; j++) {
            if (j == t) continue;
            pos  += (sa[j] >= at - MARG2);
            cert += (sa[j] >  at + MARG2);
        }
        cls[t] = (pos <= 31) ? 2 : (cert >= 32 ? 0 : 1);
    }
    __syncthreads();
    if (t < 64 && cls[t] == 1) {
        const float* wr = W_enc + (size_t)si[t] * 256;
        double s0 = 0, s1 = 0, s2 = 0, s3 = 0;
        #pragma unroll 1
        for (int d = 0; d < 256; d += 4) {
            s0 += (double)sx[d]     * (double)wr[d];
            s1 += (double)sx[d + 1] * (double)wr[d + 1];
            s2 += (double)sx[d + 2] * (double)wr[d + 2];
            s3 += (double)sx[d + 3] * (double)wr[d + 3];
        }
        double e = s0 + s1 + s2 + s3 + (double)b_enc[si[t]];
        se[t] = e > 0.0 ? e : 0.0;
    }
    __syncthreads();
    if (t == 0) {
        int ns = 0;
        bool taken[64];
        #pragma unroll 1
        for (int j = 0; j < 64; j++) {
            taken[j] = false;
            if (cls[j] == 2 && ns < 32) { seli[ns] = si[j]; selv[ns] = sa[j]; ns++; }
        }
        while (ns < 32) {
            int best = -1, bi = 1 << 30;
            double bv = -1.0;
            #pragma unroll 1
            for (int j = 0; j < 64; j++) {
                if (cls[j] == 1 && !taken[j]) {
                    if (se[j] > bv || (se[j] == bv && si[j] < bi)) {
                        best = j; bv = se[j]; bi = si[j];
                    }
                }
            }
            if (best < 0) { seli[ns] = 0; selv[ns] = 0.0f; ns++; continue; }
            taken[best] = true;
            seli[ns] = si[best]; selv[ns] = (float)se[best]; ns++;
        }
    }
    __syncthreads();
    float acc = b_dec[t];
    #pragma unroll 8
    for (int k = 0; k < 32; k++)
        acc = fmaf(selv[k], W_dec[(size_t)seli[k] * 256 + t], acc);
    out[(size_t)row * 256 + t] = acc;
}

// ============================================================================
extern "C" void kernel_launch(void* const* d_in, const int* in_sizes, int n_in,
                              void* d_out, int out_size) {
    const float* x     = (const float*)d_in[0];
    const float* W_enc = (const float*)d_in[1];
    const float* b_enc = (const float*)d_in[2];
    const float* W_dec = (const float*)d_in[3];
    const float* b_dec = (const float*)d_in[4];
    float* out = (float*)d_out;

    cudaFuncSetAttribute(encode_topk, cudaFuncAttributeMaxDynamicSharedMemorySize, SMEM_SZ);
    // 4 launches per call => ncu -s 5 -c 1 lands on encode_topk (launch #6)
    nop_k<<<1, 32>>>();
    encode_topk<<<dim3(64, 2), 256, SMEM_SZ>>>(x, W_enc, b_enc, b_dec);
    decode<<<8192, 256>>>(x, W_enc, b_enc, W_dec, b_dec, out);
    nop_k<<<1, 32>>>();
}